// round 9
// baseline (speedup 1.0000x reference)
#include <cuda_runtime.h>
#include <math.h>
#include <stdint.h>

#define BB 2
#define TT 2048
#define SS 2048
#define DM 1024
#define NH 16
#define DH 64
#define KK 1024

typedef unsigned long long ull;

// Scratch (static device globals — allocation-free rule)
__device__ float g_qn[(size_t)BB*NH*TT*DH];    // normalized+scaled Q  [b,h,t,d]
__device__ float g_kn[(size_t)BB*NH*SS*DH];    // normalized K         [b,h,s,d]
__device__ float g_vh[(size_t)BB*NH*SS*DH];    // projected V          [b,h,s,d]
__device__ float g_vals[(size_t)BB*TT*DM];     // attention output     [B,T,D]
__device__ float g_biasT[(size_t)NH*TT*SS];    // bias transposed [H,T,S], x log2e

#define LOG2E 1.4426950408889634f
#define FIXC 24.0f

// ---------------- f32x2 helpers ----------------
__device__ __forceinline__ void fma2(ull& d, ull a, ull b) {
    asm("fma.rn.f32x2 %0, %1, %2, %0;" : "+l"(d) : "l"(a), "l"(b));
}
__device__ __forceinline__ ull pk2(float x, float y) {
    ull r; asm("mov.b64 %0, {%1, %2};" : "=l"(r) : "f"(x), "f"(y)); return r;
}
__device__ __forceinline__ ull dup2(float x) { return pk2(x, x); }
__device__ __forceinline__ float2 u2(ull v) {
    float2 f; asm("mov.b64 {%0, %1}, %2;" : "=f"(f.x), "=f"(f.y) : "l"(v)); return f;
}

// ---------------- mma / ldmatrix helpers ----------------
__device__ __forceinline__ uint32_t f2tf(float f) {
    uint32_t r; asm("cvt.rna.tf32.f32 %0, %1;" : "=r"(r) : "f"(f)); return r;
}
__device__ __forceinline__ float ex2(float x) {
    float r; asm("ex2.approx.ftz.f32 %0, %1;" : "=f"(r) : "f"(x)); return r;
}
__device__ __forceinline__ void mma8(float* d, const uint32_t* a, const uint32_t* b) {
    asm("mma.sync.aligned.m16n8k8.row.col.f32.tf32.tf32.f32 "
        "{%0,%1,%2,%3}, {%4,%5,%6,%7}, {%8,%9}, {%0,%1,%2,%3};"
        : "+f"(d[0]), "+f"(d[1]), "+f"(d[2]), "+f"(d[3])
        : "r"(a[0]), "r"(a[1]), "r"(a[2]), "r"(a[3]), "r"(b[0]), "r"(b[1]));
}
__device__ __forceinline__ void ldsm4(uint32_t* r, uint32_t a) {
    asm volatile("ldmatrix.sync.aligned.m8n8.x4.shared.b16 {%0,%1,%2,%3}, [%4];"
                 : "=r"(r[0]), "=r"(r[1]), "=r"(r[2]), "=r"(r[3]) : "r"(a));
}
__device__ __forceinline__ uint32_t s2u(const void* p) {
    uint32_t a;
    asm("{ .reg .u64 t; cvta.to.shared.u64 t, %1; cvt.u32.u64 %0, t; }"
        : "=r"(a) : "l"(p));
    return a;
}
__device__ __forceinline__ void cpa16(uint32_t dst, const void* src) {
    asm volatile("cp.async.cg.shared.global [%0], [%1], 16;"
                 :: "r"(dst), "l"(src) : "memory");
}

// ---------------------------------------------------------------------------
// Tensor-core GEMM body: C = A[4096,1024] * W[1024,1024]^T.
// CTA 128x128, BK=16, 8 warps (2x4), warp tile 64x32, LDSM fragment loads.
// ---------------------------------------------------------------------------
#define LDK 20
#define ABUF (128 * LDK)
#define PRE_FLOATS (128 * 132)
#define PRE_SMEM (PRE_FLOATS * (int)sizeof(float))

__device__ __forceinline__ void gemm_mma_body(const float* __restrict__ A,
                                              const float* __restrict__ W,
                                              float* __restrict__ dst_plain,
                                              const float* __restrict__ ls,
                                              int mode, float* sm) {
    float* As = sm;
    float* Bs = sm + 2 * ABUF;
    float* Cs = sm;
    const int m0 = blockIdx.x * 128;
    const int n0 = blockIdx.y * 128;
    const int tid = threadIdx.x;
    const int wid = tid >> 5, lane = tid & 31;
    const int wm = wid >> 2, wn = wid & 3;

    // ldmatrix lane-address constants
    const int lrow = (lane & 7) + ((lane >> 3) & 1) * 8;
    const int lk4  = (lane >> 4) * 4;
    const int brow = ((lane >> 4) << 3) + (lane & 7);
    const int bk4  = ((lane >> 3) & 1) * 4;
    const uint32_t sm_u = s2u(sm);
    const uint32_t a_lane = sm_u + (uint32_t)(((wm * 64 + lrow) * LDK + lk4) * 4);
    const uint32_t b_lane = sm_u + (uint32_t)(2 * ABUF * 4) +
                            (uint32_t)(((wn * 32 + brow) * LDK + bk4) * 4);

    const int srow = tid >> 1;
    const int skc = (tid & 1) * 8;
    const float* aP = A + (size_t)(m0 + srow) * KK + skc;
    const float* wP = W + (size_t)(n0 + srow) * KK + skc;

    float d[4][4][4];
#pragma unroll
    for (int mt = 0; mt < 4; mt++)
#pragma unroll
        for (int nt = 0; nt < 4; nt++)
#pragma unroll
            for (int r = 0; r < 4; r++) d[mt][nt][r] = 0.f;

    float4 ra0, ra1, rw0, rw1;
    ra0 = *(const float4*)(aP);      ra1 = *(const float4*)(aP + 4);
    rw0 = *(const float4*)(wP);      rw1 = *(const float4*)(wP + 4);

    const int NC = KK / 16;
    for (int c = 0; c < NC; c++) {
        const int buf = c & 1;
        {
            uint32_t* ad = (uint32_t*)(As + buf * ABUF + srow * LDK + skc);
            uint32_t* bd = (uint32_t*)(Bs + buf * ABUF + srow * LDK + skc);
            ad[0] = f2tf(ra0.x); ad[1] = f2tf(ra0.y); ad[2] = f2tf(ra0.z); ad[3] = f2tf(ra0.w);
            ad[4] = f2tf(ra1.x); ad[5] = f2tf(ra1.y); ad[6] = f2tf(ra1.z); ad[7] = f2tf(ra1.w);
            bd[0] = f2tf(rw0.x); bd[1] = f2tf(rw0.y); bd[2] = f2tf(rw0.z); bd[3] = f2tf(rw0.w);
            bd[4] = f2tf(rw1.x); bd[5] = f2tf(rw1.y); bd[6] = f2tf(rw1.z); bd[7] = f2tf(rw1.w);
        }
        __syncthreads();
        if (c + 1 < NC) {
            int ko = (c + 1) * 16;
            ra0 = *(const float4*)(aP + ko);  ra1 = *(const float4*)(aP + ko + 4);
            rw0 = *(const float4*)(wP + ko);  rw1 = *(const float4*)(wP + ko + 4);
        }
        const uint32_t ab = a_lane + (uint32_t)(buf * ABUF * 4);
        const uint32_t bb = b_lane + (uint32_t)(buf * ABUF * 4);
#pragma unroll
        for (int ks = 0; ks < 2; ks++) {
            uint32_t af[4][4], bf[8];
            ldsm4(af[0], ab + ks * 32);
            ldsm4(af[1], ab + 16 * LDK * 4 + ks * 32);
            ldsm4(af[2], ab + 32 * LDK * 4 + ks * 32);
            ldsm4(af[3], ab + 48 * LDK * 4 + ks * 32);
            ldsm4(bf,     bb + ks * 32);
            ldsm4(bf + 4, bb + 16 * LDK * 4 + ks * 32);
#pragma unroll
            for (int mt = 0; mt < 4; mt++)
#pragma unroll
                for (int nt = 0; nt < 4; nt++)
                    mma8(d[mt][nt], af[mt], bf + nt * 2);
        }
        __syncthreads();
    }

    const int g = lane >> 2, tg = lane & 3;
#pragma unroll
    for (int mt = 0; mt < 4; mt++) {
        int r = wm * 64 + mt * 16 + g;
#pragma unroll
        for (int nt = 0; nt < 4; nt++) {
            int cc = wn * 32 + nt * 8 + 2 * tg;
            *(float2*)&Cs[r * 132 + cc]       = make_float2(d[mt][nt][0], d[mt][nt][1]);
            *(float2*)&Cs[(r + 8) * 132 + cc] = make_float2(d[mt][nt][2], d[mt][nt][3]);
        }
    }
    __syncthreads();

    {
        const int row = tid >> 1;
        const int half = tid & 1;
        float f[64];
        const float* src = &Cs[row * 132 + half * 64];
#pragma unroll
        for (int j = 0; j < 16; j++) {
            float4 v = *(const float4*)(src + j * 4);
            f[4 * j] = v.x; f[4 * j + 1] = v.y; f[4 * j + 2] = v.z; f[4 * j + 3] = v.w;
        }
        if (mode >= 2) {
            float ssq = 0.f;
#pragma unroll
            for (int j = 0; j < 64; j++) ssq += f[j] * f[j];
            float hs = 1.0f;
            if (mode == 3)   // fold log2e into the Q logit scale (log2-domain softmax)
                hs = expf(fminf(ls[blockIdx.y * 2 + half], 4.6051701859880914f)) * LOG2E;
            float inv = hs / fmaxf(sqrtf(ssq), 1e-12f);
#pragma unroll
            for (int j = 0; j < 64; j++) f[j] *= inv;
        }
        const int m = m0 + row;
        float* dst;
        if (mode == 0) {
            dst = dst_plain + (size_t)m * DM + n0 + half * 64;
        } else {
            int b = m >> 11, t = m & 2047;
            int h = (n0 >> 6) + half;
            float* base = (mode == 1) ? g_vh : (mode == 2) ? g_kn : g_qn;
            dst = base + (((size_t)(b * NH + h)) * TT + t) * DH;
        }
#pragma unroll
        for (int j = 0; j < 16; j++)
            *(float4*)(dst + j * 4) =
                make_float4(f[4 * j], f[4 * j + 1], f[4 * j + 2], f[4 * j + 3]);
    }
}

// ---------------------------------------------------------------------------
// Bias transpose: [T,S,H] -> [H,T,S], scaled by log2e.
// ---------------------------------------------------------------------------
__device__ __forceinline__ void transpose_body(const float* __restrict__ in, float* sm) {
    const int c = blockIdx.y * 32 + blockIdx.x;
    const int tid = threadIdx.x;
    for (int tb = 0; tb < 2; tb++) {
        const int t0 = (c * 2 + tb) * 4;
        for (int s0 = 0; s0 < SS; s0 += 64) {
#pragma unroll
            for (int tt = 0; tt < 4; tt++) {
                const float* src = in + ((size_t)(t0 + tt) * SS + s0) * NH;
#pragma unroll
                for (int p = 0; p < 4; p++) {
                    int idx = p * 256 + tid;
                    int h = idx & 15, ss = idx >> 4;
                    sm[h * 261 + tt * 64 + ss] = src[idx] * LOG2E;
                }
            }
            __syncthreads();
#pragma unroll
            for (int p = 0; p < 16; p++) {
                int idx = p * 256 + tid;
                int ss = idx & 63;
                int combo = idx >> 6;
                int tt = combo & 3, h = combo >> 2;
                g_biasT[(size_t)h * TT * SS + (size_t)(t0 + tt) * SS + s0 + ss] =
                    sm[h * 261 + tt * 64 + ss];
            }
            __syncthreads();
        }
    }
}

__global__ __launch_bounds__(256, 2) void fused_pre_kernel(const float* __restrict__ q,
                                                           const float* __restrict__ k,
                                                           const float* __restrict__ v,
                                                           const float* __restrict__ bias,
                                                           const float* __restrict__ Wqkv,
                                                           const float* __restrict__ ls) {
    extern __shared__ float sm[];
    const int z = blockIdx.z;
    if (z == 0)      gemm_mma_body(q, Wqkv, nullptr, ls, 3, sm);
    else if (z == 1) gemm_mma_body(k, Wqkv, nullptr, nullptr, 2, sm);
    else if (z == 2) gemm_mma_body(v, Wqkv, nullptr, nullptr, 1, sm);
    else             transpose_body(bias, sm);
}

__global__ __launch_bounds__(256, 2) void gemm_out_kernel(const float* __restrict__ Wout,
                                                          float* __restrict__ out) {
    extern __shared__ float sm[];
    gemm_mma_body((const float*)g_vals, Wout, out, nullptr, 0, sm);
}

// ---------------------------------------------------------------------------
// Flash attention v3: BM=128(t), BN=64(s), 256 thr.
// Bias prefetched via cp.async into the Ps buffer (consumed in-place, then
// overwritten with P). QK: FFMA2. Softmax: log2-domain fixed-offset ex2.
// PV: mma.sync tf32 with LDSM fragment loads; O frags register-resident.
// Smem: Qt[64][132] | Kt[64][68] | Vt[64][68] tf32 | Ps[128][68] | Ls[128].
// ---------------------------------------------------------------------------
#define ATT_FLOATS (64*132 + 64*68 + 64*68 + 128*68 + 128)
#define ATT_SMEM (ATT_FLOATS * (int)sizeof(float))

__global__ __launch_bounds__(256, 2) void attention_kernel() {
    extern __shared__ float sm[];
    float* Qt = sm;                        // [64][132]
    float* Kt = sm + 64 * 132;             // [64][68]
    float* Vt = Kt + 64 * 68;              // [64][68] tf32 bits
    float* Ps = Vt + 64 * 68;              // [128][68]  (bias, then P)
    float* Ls = Ps + 128 * 68;             // [128]

    const int t0 = blockIdx.x * 128;
    const int h = blockIdx.y;
    const int b = blockIdx.z;
    const int tid = threadIdx.x;
    const int tx = tid & 15, ty = tid >> 4;
    const int wid = tid >> 5, lane = tid & 31;
    const int g = lane >> 2, tg = lane & 3;
    const int wm = wid >> 1, wn = wid & 1;   // 4 x 2 warp grid (PV)

    // ldmatrix lane constants (PV)
    const int lrow = (lane & 7) + ((lane >> 3) & 1) * 8;
    const int lk4  = (lane >> 4) * 4;
    const int brow = ((lane >> 4) << 3) + (lane & 7);
    const int bk4  = ((lane >> 3) & 1) * 4;
    const uint32_t ps_u = s2u(Ps);
    const uint32_t vt_u = s2u(Vt);
    const uint32_t p_lane = ps_u + (uint32_t)(((wm * 32 + lrow) * 68 + lk4) * 4);
    const uint32_t v_lane = vt_u + (uint32_t)(((wn * 32 + brow) * 68 + bk4) * 4);

    const float* qptr  = g_qn + (((size_t)(b * NH + h)) * TT + t0) * DH;
    const float* kbase = g_kn + ((size_t)(b * NH + h)) * SS * DH;
    const float* vbase = g_vh + ((size_t)(b * NH + h)) * SS * DH;
    const float* bptr  = g_biasT + (size_t)h * TT * SS + (size_t)t0 * SS;

    // Load Q tile once, transposed: Qt[d][m]
    {
        int m = tid >> 1;
        int dc0 = (tid & 1) * 32;
        const float* qp = qptr + (size_t)m * DH + dc0;
#pragma unroll
        for (int q = 0; q < 8; q++) {
            float4 v = *(const float4*)(qp + q * 4);
            int d = dc0 + q * 4;
            Qt[(d + 0) * 132 + m] = v.x;
            Qt[(d + 1) * 132 + m] = v.y;
            Qt[(d + 2) * 132 + m] = v.z;
            Qt[(d + 3) * 132 + m] = v.w;
        }
    }

    float lsum[8];
#pragma unroll
    for (int i = 0; i < 8; i++) lsum[i] = 0.f;
    float o[2][4][4];
#pragma unroll
    for (int mt = 0; mt < 2; mt++)
#pragma unroll
        for (int nt = 0; nt < 4; nt++)
#pragma unroll
            for (int r = 0; r < 4; r++) o[mt][nt][r] = 0.f;

    for (int s0 = 0; s0 < SS; s0 += 64) {
        __syncthreads();   // prev-iter Kt/Vt/Ps readers done

        // prefetch this tile's bias into Ps (each thread copies its own cells)
#pragma unroll
        for (int i = 0; i < 8; i++) {
            uint32_t dst = ps_u + (uint32_t)(((ty * 8 + i) * 68 + tx * 4) * 4);
            cpa16(dst, bptr + (size_t)(ty * 8 + i) * SS + s0 + tx * 4);
        }
        asm volatile("cp.async.commit_group;" ::: "memory");

        // load K (fp32, d-major) and V (tf32, dh-major) transposed tiles
        {
            int s = tid >> 2;
            int dc = (tid & 3) * 16;
            const float* kp = kbase + (size_t)(s0 + s) * DH + dc;
            const float* vp = vbase + (size_t)(s0 + s) * DH + dc;
#pragma unroll
            for (int q = 0; q < 4; q++) {
                float4 kv = *(const float4*)(kp + q * 4);
                int d = dc + q * 4;
                Kt[(d + 0) * 68 + s] = kv.x;
                Kt[(d + 1) * 68 + s] = kv.y;
                Kt[(d + 2) * 68 + s] = kv.z;
                Kt[(d + 3) * 68 + s] = kv.w;
            }
            uint32_t* Vb = (uint32_t*)Vt;
#pragma unroll
            for (int q = 0; q < 4; q++) {
                float4 vv = *(const float4*)(vp + q * 4);
                int d = dc + q * 4;
                Vb[(d + 0) * 68 + s] = f2tf(vv.x);
                Vb[(d + 1) * 68 + s] = f2tf(vv.y);
                Vb[(d + 2) * 68 + s] = f2tf(vv.z);
                Vb[(d + 3) * 68 + s] = f2tf(vv.w);
            }
        }
        __syncthreads();

        // S = Q K^T (f32x2 FFMA2, pairs along m); logits already x log2e
        ull acc2[4][4];
#pragma unroll
        for (int i2 = 0; i2 < 4; i2++)
#pragma unroll
            for (int j = 0; j < 4; j++) acc2[i2][j] = 0ull;
#pragma unroll 8
        for (int d = 0; d < 64; d++) {
            ulonglong2 a0 = *(const ulonglong2*)&Qt[d * 132 + ty * 8];
            ulonglong2 a1 = *(const ulonglong2*)&Qt[d * 132 + ty * 8 + 4];
            float4 bv = *(const float4*)&Kt[d * 68 + tx * 4];
            float bj[4] = {bv.x, bv.y, bv.z, bv.w};
#pragma unroll
            for (int j = 0; j < 4; j++) {
                ull bd = dup2(bj[j]);
                fma2(acc2[0][j], a0.x, bd);
                fma2(acc2[1][j], a0.y, bd);
                fma2(acc2[2][j], a1.x, bd);
                fma2(acc2[3][j], a1.y, bd);
            }
        }

        // bias (from Ps, prefetched) + ex2, write P back into Ps (raw fp32)
        asm volatile("cp.async.wait_group 0;" ::: "memory");
#pragma unroll
        for (int i2 = 0; i2 < 4; i2++) {
#pragma unroll
            for (int half = 0; half < 2; half++) {
                int i = 2 * i2 + half;
                float* prow = &Ps[(ty * 8 + i) * 68 + tx * 4];
                float4 bb = *(const float4*)prow;
                float2 f0 = u2(acc2[i2][0]);
                float2 f1 = u2(acc2[i2][1]);
                float2 f2v = u2(acc2[i2][2]);
                float2 f3 = u2(acc2[i2][3]);
                float p0 = ex2((half ? f0.y : f0.x) + bb.x - FIXC);
                float p1 = ex2((half ? f1.y : f1.x) + bb.y - FIXC);
                float p2 = ex2((half ? f2v.y : f2v.x) + bb.z - FIXC);
                float p3 = ex2((half ? f3.y : f3.x) + bb.w - FIXC);
                lsum[i] += (p0 + p1) + (p2 + p3);
                *(float4*)prow = make_float4(p0, p1, p2, p3);
            }
        }
        __syncthreads();

        // O += P V (mma.sync tf32, LDSM fragments)
#pragma unroll
        for (int kk = 0; kk < 8; kk++) {
            uint32_t pf[2][4], vf[8];
            ldsm4(pf[0], p_lane + kk * 32);
            ldsm4(pf[1], p_lane + 16 * 68 * 4 + kk * 32);
            ldsm4(vf,     v_lane + kk * 32);
            ldsm4(vf + 4, v_lane + 16 * 68 * 4 + kk * 32);
#pragma unroll
            for (int nt = 0; nt < 4; nt++) {
                mma8(o[0][nt], pf[0], vf + nt * 2);
                mma8(o[1][nt], pf[1], vf + nt * 2);
            }
        }
    }

    // reduce lsum across the 16-lane tx group; store per-row sums
    {
        float red[8];
#pragma unroll
        for (int i = 0; i < 8; i++) {
            float rs = lsum[i];
            rs += __shfl_xor_sync(0xffffffffu, rs, 1);
            rs += __shfl_xor_sync(0xffffffffu, rs, 2);
            rs += __shfl_xor_sync(0xffffffffu, rs, 4);
            rs += __shfl_xor_sync(0xffffffffu, rs, 8);
            red[i] = rs;
        }
        if (tx == 0) {
#pragma unroll
            for (int i = 0; i < 8; i++) Ls[ty * 8 + i] = red[i];
        }
    }
    __syncthreads();

    // epilogue: normalize O fragments and write to g_vals [B,T,D]
#pragma unroll
    for (int mt = 0; mt < 2; mt++) {
        int r = wm * 32 + mt * 16 + g;
        float inv0 = 1.0f / Ls[r];
        float inv1 = 1.0f / Ls[r + 8];
        float* d0 = g_vals + ((size_t)(b * TT) + t0 + r) * DM + h * DH;
        float* d1 = g_vals + ((size_t)(b * TT) + t0 + r + 8) * DM + h * DH;
#pragma unroll
        for (int nt = 0; nt < 4; nt++) {
            int c = wn * 32 + nt * 8 + 2 * tg;
            *(float2*)(d0 + c) = make_float2(o[mt][nt][0] * inv0, o[mt][nt][1] * inv0);
            *(float2*)(d1 + c) = make_float2(o[mt][nt][2] * inv1, o[mt][nt][3] * inv1);
        }
    }
}

// ---------------------------------------------------------------------------
extern "C" void kernel_launch(void* const* d_in, const int* in_sizes, int n_in,
                              void* d_out, int out_size) {
    const float* q    = (const float*)d_in[0];
    const float* k    = (const float*)d_in[1];
    const float* v    = (const float*)d_in[2];
    const float* bias = (const float*)d_in[3];
    const float* Wqkv = (const float*)d_in[4];
    const float* Wout = (const float*)d_in[5];
    const float* ls   = (const float*)d_in[6];
    float* out = (float*)d_out;

    cudaFuncSetAttribute(attention_kernel,
                         cudaFuncAttributeMaxDynamicSharedMemorySize, ATT_SMEM);
    cudaFuncSetAttribute(fused_pre_kernel,
                         cudaFuncAttributeMaxDynamicSharedMemorySize, PRE_SMEM);
    cudaFuncSetAttribute(gemm_out_kernel,
                         cudaFuncAttributeMaxDynamicSharedMemorySize, PRE_SMEM);

    fused_pre_kernel<<<dim3(32, 8, 4), 256, PRE_SMEM>>>(q, k, v, bias, Wqkv, ls);

    attention_kernel<<<dim3(TT / 128, NH, BB), 256, ATT_SMEM>>>();

    gemm_out_kernel<<<dim3(32, 8), 256, PRE_SMEM>>>(Wout, out);
}

// round 10
// speedup vs baseline: 1.4184x; 1.4184x over previous
#include <cuda_runtime.h>
#include <math.h>
#include <stdint.h>

#define BB 2
#define TT 2048
#define SS 2048
#define DM 1024
#define NH 16
#define DH 64
#define KK 1024

typedef unsigned long long ull;

// Scratch (static device globals — allocation-free rule)
__device__ float g_qn[(size_t)BB*NH*TT*DH];    // normalized+scaled Q  [b,h,t,d]
__device__ float g_kn[(size_t)BB*NH*SS*DH];    // normalized K         [b,h,s,d]
__device__ float g_vh[(size_t)BB*NH*SS*DH];    // projected V          [b,h,s,d]
__device__ float g_vals[(size_t)BB*TT*DM];     // attention output     [B,T,D]
__device__ float g_biasT[(size_t)NH*TT*SS];    // bias transposed [H,T,S], x log2e

#define LOG2E 1.4426950408889634f
#define FIXC 24.0f

// ---------------- f32x2 helpers ----------------
__device__ __forceinline__ void fma2(ull& d, ull a, ull b) {
    asm("fma.rn.f32x2 %0, %1, %2, %0;" : "+l"(d) : "l"(a), "l"(b));
}
__device__ __forceinline__ ull pk2(float x, float y) {
    ull r; asm("mov.b64 %0, {%1, %2};" : "=l"(r) : "f"(x), "f"(y)); return r;
}
__device__ __forceinline__ ull dup2(float x) { return pk2(x, x); }
__device__ __forceinline__ float2 u2(ull v) {
    float2 f; asm("mov.b64 {%0, %1}, %2;" : "=f"(f.x), "=f"(f.y) : "l"(v)); return f;
}

// ---------------- mma.sync tf32 helpers ----------------
__device__ __forceinline__ uint32_t f2tf(float f) {
    uint32_t r; asm("cvt.rna.tf32.f32 %0, %1;" : "=r"(r) : "f"(f)); return r;
}
__device__ __forceinline__ float ex2(float x) {
    float r; asm("ex2.approx.ftz.f32 %0, %1;" : "=f"(r) : "f"(x)); return r;
}
__device__ __forceinline__ void mma8(float* d, const uint32_t* a, const uint32_t* b) {
    asm("mma.sync.aligned.m16n8k8.row.col.f32.tf32.tf32.f32 "
        "{%0,%1,%2,%3}, {%4,%5,%6,%7}, {%8,%9}, {%0,%1,%2,%3};"
        : "+f"(d[0]), "+f"(d[1]), "+f"(d[2]), "+f"(d[3])
        : "r"(a[0]), "r"(a[1]), "r"(a[2]), "r"(a[3]), "r"(b[0]), "r"(b[1]));
}
__device__ __forceinline__ uint32_t s2u(const void* p) {
    uint32_t a;
    asm("{ .reg .u64 t; cvta.to.shared.u64 t, %1; cvt.u32.u64 %0, t; }"
        : "=r"(a) : "l"(p));
    return a;
}
__device__ __forceinline__ void cpa16(uint32_t dst, const void* src) {
    asm volatile("cp.async.cg.shared.global [%0], [%1], 16;"
                 :: "r"(dst), "l"(src) : "memory");
}

// ---------------------------------------------------------------------------
// Tensor-core GEMM body (R8-verbatim, scalar fragment loads):
// C = A[4096,1024] * W[1024,1024]^T. CTA 128x128, BK=16, 8 warps (2x4).
// ---------------------------------------------------------------------------
#define LDK 20
#define ABUF (128 * LDK)
#define PRE_FLOATS (128 * 132)
#define PRE_SMEM (PRE_FLOATS * (int)sizeof(float))

__device__ __forceinline__ void gemm_mma_body(const float* __restrict__ A,
                                              const float* __restrict__ W,
                                              float* __restrict__ dst_plain,
                                              const float* __restrict__ ls,
                                              int mode, float* sm) {
    float* As = sm;
    float* Bs = sm + 2 * ABUF;
    float* Cs = sm;
    const int m0 = blockIdx.x * 128;
    const int n0 = blockIdx.y * 128;
    const int tid = threadIdx.x;
    const int wid = tid >> 5, lane = tid & 31;
    const int wm = wid >> 2, wn = wid & 3;
    const int g = lane >> 2, tg = lane & 3;

    const int srow = tid >> 1;
    const int skc = (tid & 1) * 8;
    const float* aP = A + (size_t)(m0 + srow) * KK + skc;
    const float* wP = W + (size_t)(n0 + srow) * KK + skc;

    float d[4][4][4];
#pragma unroll
    for (int mt = 0; mt < 4; mt++)
#pragma unroll
        for (int nt = 0; nt < 4; nt++)
#pragma unroll
            for (int r = 0; r < 4; r++) d[mt][nt][r] = 0.f;

    float4 ra0, ra1, rw0, rw1;
    ra0 = *(const float4*)(aP);      ra1 = *(const float4*)(aP + 4);
    rw0 = *(const float4*)(wP);      rw1 = *(const float4*)(wP + 4);

    const int NC = KK / 16;
    for (int c = 0; c < NC; c++) {
        const int buf = c & 1;
        {
            uint32_t* ad = (uint32_t*)(As + buf * ABUF + srow * LDK + skc);
            uint32_t* bd = (uint32_t*)(Bs + buf * ABUF + srow * LDK + skc);
            ad[0] = f2tf(ra0.x); ad[1] = f2tf(ra0.y); ad[2] = f2tf(ra0.z); ad[3] = f2tf(ra0.w);
            ad[4] = f2tf(ra1.x); ad[5] = f2tf(ra1.y); ad[6] = f2tf(ra1.z); ad[7] = f2tf(ra1.w);
            bd[0] = f2tf(rw0.x); bd[1] = f2tf(rw0.y); bd[2] = f2tf(rw0.z); bd[3] = f2tf(rw0.w);
            bd[4] = f2tf(rw1.x); bd[5] = f2tf(rw1.y); bd[6] = f2tf(rw1.z); bd[7] = f2tf(rw1.w);
        }
        __syncthreads();
        if (c + 1 < NC) {
            int ko = (c + 1) * 16;
            ra0 = *(const float4*)(aP + ko);  ra1 = *(const float4*)(aP + ko + 4);
            rw0 = *(const float4*)(wP + ko);  rw1 = *(const float4*)(wP + ko + 4);
        }
        const uint32_t* Ab = (const uint32_t*)(As + buf * ABUF);
        const uint32_t* Bb = (const uint32_t*)(Bs + buf * ABUF);
#pragma unroll
        for (int ks = 0; ks < 2; ks++) {
            const int k = ks * 8 + tg;
            uint32_t af[4][4], bf[4][2];
#pragma unroll
            for (int mt = 0; mt < 4; mt++) {
                int r = wm * 64 + mt * 16 + g;
                af[mt][0] = Ab[r * LDK + k];
                af[mt][1] = Ab[(r + 8) * LDK + k];
                af[mt][2] = Ab[r * LDK + k + 4];
                af[mt][3] = Ab[(r + 8) * LDK + k + 4];
            }
#pragma unroll
            for (int nt = 0; nt < 4; nt++) {
                int n = wn * 32 + nt * 8 + g;
                bf[nt][0] = Bb[n * LDK + k];
                bf[nt][1] = Bb[n * LDK + k + 4];
            }
#pragma unroll
            for (int mt = 0; mt < 4; mt++)
#pragma unroll
                for (int nt = 0; nt < 4; nt++)
                    mma8(d[mt][nt], af[mt], bf[nt]);
        }
        __syncthreads();
    }

#pragma unroll
    for (int mt = 0; mt < 4; mt++) {
        int r = wm * 64 + mt * 16 + g;
#pragma unroll
        for (int nt = 0; nt < 4; nt++) {
            int cc = wn * 32 + nt * 8 + 2 * tg;
            *(float2*)&Cs[r * 132 + cc]       = make_float2(d[mt][nt][0], d[mt][nt][1]);
            *(float2*)&Cs[(r + 8) * 132 + cc] = make_float2(d[mt][nt][2], d[mt][nt][3]);
        }
    }
    __syncthreads();

    {
        const int row = tid >> 1;
        const int half = tid & 1;
        float f[64];
        const float* src = &Cs[row * 132 + half * 64];
#pragma unroll
        for (int j = 0; j < 16; j++) {
            float4 v = *(const float4*)(src + j * 4);
            f[4 * j] = v.x; f[4 * j + 1] = v.y; f[4 * j + 2] = v.z; f[4 * j + 3] = v.w;
        }
        if (mode >= 2) {
            float ssq = 0.f;
#pragma unroll
            for (int j = 0; j < 64; j++) ssq += f[j] * f[j];
            float hs = 1.0f;
            if (mode == 3)   // fold log2e into Q's logit scale (log2-domain softmax)
                hs = expf(fminf(ls[blockIdx.y * 2 + half], 4.6051701859880914f)) * LOG2E;
            float inv = hs / fmaxf(sqrtf(ssq), 1e-12f);
#pragma unroll
            for (int j = 0; j < 64; j++) f[j] *= inv;
        }
        const int m = m0 + row;
        float* dst;
        if (mode == 0) {
            dst = dst_plain + (size_t)m * DM + n0 + half * 64;
        } else {
            int b = m >> 11, t = m & 2047;
            int h = (n0 >> 6) + half;
            float* base = (mode == 1) ? g_vh : (mode == 2) ? g_kn : g_qn;
            dst = base + (((size_t)(b * NH + h)) * TT + t) * DH;
        }
#pragma unroll
        for (int j = 0; j < 16; j++)
            *(float4*)(dst + j * 4) =
                make_float4(f[4 * j], f[4 * j + 1], f[4 * j + 2], f[4 * j + 3]);
    }
}

// ---------------------------------------------------------------------------
// Bias transpose: [T,S,H] -> [H,T,S], scaled by log2e.
// ---------------------------------------------------------------------------
__device__ __forceinline__ void transpose_body(const float* __restrict__ in, float* sm) {
    const int c = blockIdx.y * 32 + blockIdx.x;
    const int tid = threadIdx.x;
    for (int tb = 0; tb < 2; tb++) {
        const int t0 = (c * 2 + tb) * 4;
        for (int s0 = 0; s0 < SS; s0 += 64) {
#pragma unroll
            for (int tt = 0; tt < 4; tt++) {
                const float* src = in + ((size_t)(t0 + tt) * SS + s0) * NH;
#pragma unroll
                for (int p = 0; p < 4; p++) {
                    int idx = p * 256 + tid;
                    int h = idx & 15, ss = idx >> 4;
                    sm[h * 261 + tt * 64 + ss] = src[idx] * LOG2E;
                }
            }
            __syncthreads();
#pragma unroll
            for (int p = 0; p < 16; p++) {
                int idx = p * 256 + tid;
                int ss = idx & 63;
                int combo = idx >> 6;
                int tt = combo & 3, h = combo >> 2;
                g_biasT[(size_t)h * TT * SS + (size_t)(t0 + tt) * SS + s0 + ss] =
                    sm[h * 261 + tt * 64 + ss];
            }
            __syncthreads();
        }
    }
}

__global__ __launch_bounds__(256, 2) void fused_pre_kernel(const float* __restrict__ q,
                                                           const float* __restrict__ k,
                                                           const float* __restrict__ v,
                                                           const float* __restrict__ bias,
                                                           const float* __restrict__ Wqkv,
                                                           const float* __restrict__ ls) {
    extern __shared__ float sm[];
    const int z = blockIdx.z;
    if (z == 0)      gemm_mma_body(q, Wqkv, nullptr, ls, 3, sm);
    else if (z == 1) gemm_mma_body(k, Wqkv, nullptr, nullptr, 2, sm);
    else if (z == 2) gemm_mma_body(v, Wqkv, nullptr, nullptr, 1, sm);
    else             transpose_body(bias, sm);
}

__global__ __launch_bounds__(256, 2) void gemm_out_kernel(const float* __restrict__ Wout,
                                                          float* __restrict__ out) {
    extern __shared__ float sm[];
    gemm_mma_body((const float*)g_vals, Wout, out, nullptr, 0, sm);
}

// ---------------------------------------------------------------------------
// Flash attention (R8 structure + cp.async bias prefetch + log2 ex2 softmax):
// BM=128(t), BN=64(s), 256 thr. QK: FFMA2 8x4 micro. PV: mma.sync tf32 with
// scalar fragment LDS (R8 pattern). P stored as raw fp32 (tf32-truncated by HW).
// Smem: Qt[64][132] | Kt[64][68] | Vt[64][68] tf32 | Ps[128][68] | Ls[128].
// ---------------------------------------------------------------------------
#define ATT_FLOATS (64*132 + 64*68 + 64*68 + 128*68 + 128)
#define ATT_SMEM (ATT_FLOATS * (int)sizeof(float))

__global__ __launch_bounds__(256, 2) void attention_kernel() {
    extern __shared__ float sm[];
    float* Qt = sm;                        // [64][132]
    float* Kt = sm + 64 * 132;             // [64][68]
    float* Vt = Kt + 64 * 68;              // [64][68] tf32 bits
    float* Ps = Vt + 64 * 68;              // [128][68]  (bias, then P)
    float* Ls = Ps + 128 * 68;             // [128]

    const int t0 = blockIdx.x * 128;
    const int h = blockIdx.y;
    const int b = blockIdx.z;
    const int tid = threadIdx.x;
    const int tx = tid & 15, ty = tid >> 4;
    const int wid = tid >> 5, lane = tid & 31;
    const int g = lane >> 2, tg = lane & 3;
    const int wm = wid >> 1, wn = wid & 1;   // 4 x 2 warp grid (PV)

    const uint32_t ps_u = s2u(Ps);

    const float* qptr  = g_qn + (((size_t)(b * NH + h)) * TT + t0) * DH;
    const float* kbase = g_kn + ((size_t)(b * NH + h)) * SS * DH;
    const float* vbase = g_vh + ((size_t)(b * NH + h)) * SS * DH;
    const float* bptr  = g_biasT + (size_t)h * TT * SS + (size_t)t0 * SS;

    // Load Q tile once, transposed: Qt[d][m]
    {
        int m = tid >> 1;
        int dc0 = (tid & 1) * 32;
        const float* qp = qptr + (size_t)m * DH + dc0;
#pragma unroll
        for (int q = 0; q < 8; q++) {
            float4 v = *(const float4*)(qp + q * 4);
            int d = dc0 + q * 4;
            Qt[(d + 0) * 132 + m] = v.x;
            Qt[(d + 1) * 132 + m] = v.y;
            Qt[(d + 2) * 132 + m] = v.z;
            Qt[(d + 3) * 132 + m] = v.w;
        }
    }

    float lsum[8];
#pragma unroll
    for (int i = 0; i < 8; i++) lsum[i] = 0.f;
    float o[2][4][4];
#pragma unroll
    for (int mt = 0; mt < 2; mt++)
#pragma unroll
        for (int nt = 0; nt < 4; nt++)
#pragma unroll
            for (int r = 0; r < 4; r++) o[mt][nt][r] = 0.f;

    for (int s0 = 0; s0 < SS; s0 += 64) {
        __syncthreads();   // prev-iter Kt/Vt/Ps readers done

        // prefetch this tile's bias into Ps (each thread copies its own cells)
#pragma unroll
        for (int i = 0; i < 8; i++) {
            uint32_t dst = ps_u + (uint32_t)(((ty * 8 + i) * 68 + tx * 4) * 4);
            cpa16(dst, bptr + (size_t)(ty * 8 + i) * SS + s0 + tx * 4);
        }
        asm volatile("cp.async.commit_group;" ::: "memory");

        // load K (fp32, d-major) and V (tf32, dh-major) transposed tiles
        {
            int s = tid >> 2;
            int dc = (tid & 3) * 16;
            const float* kp = kbase + (size_t)(s0 + s) * DH + dc;
            const float* vp = vbase + (size_t)(s0 + s) * DH + dc;
#pragma unroll
            for (int q = 0; q < 4; q++) {
                float4 kv = *(const float4*)(kp + q * 4);
                int d = dc + q * 4;
                Kt[(d + 0) * 68 + s] = kv.x;
                Kt[(d + 1) * 68 + s] = kv.y;
                Kt[(d + 2) * 68 + s] = kv.z;
                Kt[(d + 3) * 68 + s] = kv.w;
            }
            uint32_t* Vb = (uint32_t*)Vt;
#pragma unroll
            for (int q = 0; q < 4; q++) {
                float4 vv = *(const float4*)(vp + q * 4);
                int d = dc + q * 4;
                Vb[(d + 0) * 68 + s] = f2tf(vv.x);
                Vb[(d + 1) * 68 + s] = f2tf(vv.y);
                Vb[(d + 2) * 68 + s] = f2tf(vv.z);
                Vb[(d + 3) * 68 + s] = f2tf(vv.w);
            }
        }
        __syncthreads();

        // S = Q K^T (f32x2 FFMA2, pairs along m); Q already scaled by log2e
        ull acc2[4][4];
#pragma unroll
        for (int i2 = 0; i2 < 4; i2++)
#pragma unroll
            for (int j = 0; j < 4; j++) acc2[i2][j] = 0ull;
#pragma unroll 8
        for (int d = 0; d < 64; d++) {
            ulonglong2 a0 = *(const ulonglong2*)&Qt[d * 132 + ty * 8];
            ulonglong2 a1 = *(const ulonglong2*)&Qt[d * 132 + ty * 8 + 4];
            float4 bv = *(const float4*)&Kt[d * 68 + tx * 4];
            float bj[4] = {bv.x, bv.y, bv.z, bv.w};
#pragma unroll
            for (int j = 0; j < 4; j++) {
                ull bd = dup2(bj[j]);
                fma2(acc2[0][j], a0.x, bd);
                fma2(acc2[1][j], a0.y, bd);
                fma2(acc2[2][j], a1.x, bd);
                fma2(acc2[3][j], a1.y, bd);
            }
        }

        // bias (prefetched in Ps) + ex2, write raw-fp32 P back into Ps
        asm volatile("cp.async.wait_group 0;" ::: "memory");
        __syncwarp();
#pragma unroll
        for (int i2 = 0; i2 < 4; i2++) {
#pragma unroll
            for (int half = 0; half < 2; half++) {
                int i = 2 * i2 + half;
                float* prow = &Ps[(ty * 8 + i) * 68 + tx * 4];
                float4 bb = *(const float4*)prow;
                float2 f0 = u2(acc2[i2][0]);
                float2 f1 = u2(acc2[i2][1]);
                float2 f2v = u2(acc2[i2][2]);
                float2 f3 = u2(acc2[i2][3]);
                float p0 = ex2((half ? f0.y : f0.x) + bb.x - FIXC);
                float p1 = ex2((half ? f1.y : f1.x) + bb.y - FIXC);
                float p2 = ex2((half ? f2v.y : f2v.x) + bb.z - FIXC);
                float p3 = ex2((half ? f3.y : f3.x) + bb.w - FIXC);
                lsum[i] += (p0 + p1) + (p2 + p3);
                *(float4*)prow = make_float4(p0, p1, p2, p3);
            }
        }
        __syncthreads();

        // O += P V (mma.sync tf32, scalar fragment loads — R8 pattern)
        const uint32_t* Pr = (const uint32_t*)Ps;
        const uint32_t* Vr = (const uint32_t*)Vt;
#pragma unroll
        for (int kk = 0; kk < 8; kk++) {
            const int k = kk * 8 + tg;
            uint32_t af[2][4];
#pragma unroll
            for (int mt = 0; mt < 2; mt++) {
                int r = wm * 32 + mt * 16 + g;
                af[mt][0] = Pr[r * 68 + k];
                af[mt][1] = Pr[(r + 8) * 68 + k];
                af[mt][2] = Pr[r * 68 + k + 4];
                af[mt][3] = Pr[(r + 8) * 68 + k + 4];
            }
#pragma unroll
            for (int nt = 0; nt < 4; nt++) {
                int n = wn * 32 + nt * 8 + g;
                uint32_t bf[2];
                bf[0] = Vr[n * 68 + k];
                bf[1] = Vr[n * 68 + k + 4];
                mma8(o[0][nt], af[0], bf);
                mma8(o[1][nt], af[1], bf);
            }
        }
    }

    // reduce lsum across the 16-lane tx group; store per-row sums
    {
        float red[8];
#pragma unroll
        for (int i = 0; i < 8; i++) {
            float rs = lsum[i];
            rs += __shfl_xor_sync(0xffffffffu, rs, 1);
            rs += __shfl_xor_sync(0xffffffffu, rs, 2);
            rs += __shfl_xor_sync(0xffffffffu, rs, 4);
            rs += __shfl_xor_sync(0xffffffffu, rs, 8);
            red[i] = rs;
        }
        if (tx == 0) {
#pragma unroll
            for (int i = 0; i < 8; i++) Ls[ty * 8 + i] = red[i];
        }
    }
    __syncthreads();

    // epilogue: normalize O fragments and write to g_vals [B,T,D]
#pragma unroll
    for (int mt = 0; mt < 2; mt++) {
        int r = wm * 32 + mt * 16 + g;
        float inv0 = 1.0f / Ls[r];
        float inv1 = 1.0f / Ls[r + 8];
        float* d0 = g_vals + ((size_t)(b * TT) + t0 + r) * DM + h * DH;
        float* d1 = g_vals + ((size_t)(b * TT) + t0 + r + 8) * DM + h * DH;
#pragma unroll
        for (int nt = 0; nt < 4; nt++) {
            int c = wn * 32 + nt * 8 + 2 * tg;
            *(float2*)(d0 + c) = make_float2(o[mt][nt][0] * inv0, o[mt][nt][1] * inv0);
            *(float2*)(d1 + c) = make_float2(o[mt][nt][2] * inv1, o[mt][nt][3] * inv1);
        }
    }
}

// ---------------------------------------------------------------------------
extern "C" void kernel_launch(void* const* d_in, const int* in_sizes, int n_in,
                              void* d_out, int out_size) {
    const float* q    = (const float*)d_in[0];
    const float* k    = (const float*)d_in[1];
    const float* v    = (const float*)d_in[2];
    const float* bias = (const float*)d_in[3];
    const float* Wqkv = (const float*)d_in[4];
    const float* Wout = (const float*)d_in[5];
    const float* ls   = (const float*)d_in[6];
    float* out = (float*)d_out;

    cudaFuncSetAttribute(attention_kernel,
                         cudaFuncAttributeMaxDynamicSharedMemorySize, ATT_SMEM);
    cudaFuncSetAttribute(fused_pre_kernel,
                         cudaFuncAttributeMaxDynamicSharedMemorySize, PRE_SMEM);
    cudaFuncSetAttribute(gemm_out_kernel,
                         cudaFuncAttributeMaxDynamicSharedMemorySize, PRE_SMEM);

    fused_pre_kernel<<<dim3(32, 8, 4), 256, PRE_SMEM>>>(q, k, v, bias, Wqkv, ls);

    attention_kernel<<<dim3(TT / 128, NH, BB), 256, ATT_SMEM>>>();

    gemm_out_kernel<<<dim3(32, 8), 256, PRE_SMEM>>>(Wout, out);
}

// round 11
// speedup vs baseline: 1.7602x; 1.2410x over previous
#include <cuda_runtime.h>
#include <math.h>
#include <stdint.h>

#define BB 2
#define TT 2048
#define SS 2048
#define DM 1024
#define NH 16
#define DH 64
#define KK 1024

typedef unsigned long long ull;

// Scratch (static device globals — allocation-free rule)
__device__ float g_qn[(size_t)BB*NH*TT*DH];    // normalized+scaled Q  [b,h,t,d]
__device__ float g_kn[(size_t)BB*NH*SS*DH];    // normalized K         [b,h,s,d]
__device__ float g_vh[(size_t)BB*NH*SS*DH];    // projected V          [b,h,s,d]
__device__ float g_vals[(size_t)BB*TT*DM];     // attention output     [B,T,D]
__device__ float g_biasT[(size_t)NH*TT*SS];    // bias transposed [H,T,S], x log2e

#define LOG2E 1.4426950408889634f
#define FIXC 24.0f

// ---------------- mma.sync tf32 helpers ----------------
__device__ __forceinline__ uint32_t f2tf(float f) {
    uint32_t r; asm("cvt.rna.tf32.f32 %0, %1;" : "=r"(r) : "f"(f)); return r;
}
__device__ __forceinline__ float ex2(float x) {
    float r; asm("ex2.approx.ftz.f32 %0, %1;" : "=f"(r) : "f"(x)); return r;
}
__device__ __forceinline__ void mma8(float* d, const uint32_t* a, const uint32_t* b) {
    asm("mma.sync.aligned.m16n8k8.row.col.f32.tf32.tf32.f32 "
        "{%0,%1,%2,%3}, {%4,%5,%6,%7}, {%8,%9}, {%0,%1,%2,%3};"
        : "+f"(d[0]), "+f"(d[1]), "+f"(d[2]), "+f"(d[3])
        : "r"(a[0]), "r"(a[1]), "r"(a[2]), "r"(a[3]), "r"(b[0]), "r"(b[1]));
}
__device__ __forceinline__ uint32_t s2u(const void* p) {
    uint32_t a;
    asm("{ .reg .u64 t; cvta.to.shared.u64 t, %1; cvt.u32.u64 %0, t; }"
        : "=r"(a) : "l"(p));
    return a;
}
__device__ __forceinline__ void cpa16(uint32_t dst, const void* src) {
    asm volatile("cp.async.cg.shared.global [%0], [%1], 16;"
                 :: "r"(dst), "l"(src) : "memory");
}

// ---------------------------------------------------------------------------
// Tensor-core GEMM body (R8/R10-verbatim): C = A[4096,1024] * W[1024,1024]^T.
// CTA 128x128, BK=16, 8 warps (2x4), scalar fragment loads.
// ---------------------------------------------------------------------------
#define LDK 20
#define ABUF (128 * LDK)
#define PRE_FLOATS (128 * 132)
#define PRE_SMEM (PRE_FLOATS * (int)sizeof(float))

__device__ __forceinline__ void gemm_mma_body(const float* __restrict__ A,
                                              const float* __restrict__ W,
                                              float* __restrict__ dst_plain,
                                              const float* __restrict__ ls,
                                              int mode, float* sm) {
    float* As = sm;
    float* Bs = sm + 2 * ABUF;
    float* Cs = sm;
    const int m0 = blockIdx.x * 128;
    const int n0 = blockIdx.y * 128;
    const int tid = threadIdx.x;
    const int wid = tid >> 5, lane = tid & 31;
    const int wm = wid >> 2, wn = wid & 3;
    const int g = lane >> 2, tg = lane & 3;

    const int srow = tid >> 1;
    const int skc = (tid & 1) * 8;
    const float* aP = A + (size_t)(m0 + srow) * KK + skc;
    const float* wP = W + (size_t)(n0 + srow) * KK + skc;

    float d[4][4][4];
#pragma unroll
    for (int mt = 0; mt < 4; mt++)
#pragma unroll
        for (int nt = 0; nt < 4; nt++)
#pragma unroll
            for (int r = 0; r < 4; r++) d[mt][nt][r] = 0.f;

    float4 ra0, ra1, rw0, rw1;
    ra0 = *(const float4*)(aP);      ra1 = *(const float4*)(aP + 4);
    rw0 = *(const float4*)(wP);      rw1 = *(const float4*)(wP + 4);

    const int NC = KK / 16;
    for (int c = 0; c < NC; c++) {
        const int buf = c & 1;
        {
            uint32_t* ad = (uint32_t*)(As + buf * ABUF + srow * LDK + skc);
            uint32_t* bd = (uint32_t*)(Bs + buf * ABUF + srow * LDK + skc);
            ad[0] = f2tf(ra0.x); ad[1] = f2tf(ra0.y); ad[2] = f2tf(ra0.z); ad[3] = f2tf(ra0.w);
            ad[4] = f2tf(ra1.x); ad[5] = f2tf(ra1.y); ad[6] = f2tf(ra1.z); ad[7] = f2tf(ra1.w);
            bd[0] = f2tf(rw0.x); bd[1] = f2tf(rw0.y); bd[2] = f2tf(rw0.z); bd[3] = f2tf(rw0.w);
            bd[4] = f2tf(rw1.x); bd[5] = f2tf(rw1.y); bd[6] = f2tf(rw1.z); bd[7] = f2tf(rw1.w);
        }
        __syncthreads();
        if (c + 1 < NC) {
            int ko = (c + 1) * 16;
            ra0 = *(const float4*)(aP + ko);  ra1 = *(const float4*)(aP + ko + 4);
            rw0 = *(const float4*)(wP + ko);  rw1 = *(const float4*)(wP + ko + 4);
        }
        const uint32_t* Ab = (const uint32_t*)(As + buf * ABUF);
        const uint32_t* Bb = (const uint32_t*)(Bs + buf * ABUF);
#pragma unroll
        for (int ks = 0; ks < 2; ks++) {
            const int k = ks * 8 + tg;
            uint32_t af[4][4], bf[4][2];
#pragma unroll
            for (int mt = 0; mt < 4; mt++) {
                int r = wm * 64 + mt * 16 + g;
                af[mt][0] = Ab[r * LDK + k];
                af[mt][1] = Ab[(r + 8) * LDK + k];
                af[mt][2] = Ab[r * LDK + k + 4];
                af[mt][3] = Ab[(r + 8) * LDK + k + 4];
            }
#pragma unroll
            for (int nt = 0; nt < 4; nt++) {
                int n = wn * 32 + nt * 8 + g;
                bf[nt][0] = Bb[n * LDK + k];
                bf[nt][1] = Bb[n * LDK + k + 4];
            }
#pragma unroll
            for (int mt = 0; mt < 4; mt++)
#pragma unroll
                for (int nt = 0; nt < 4; nt++)
                    mma8(d[mt][nt], af[mt], bf[nt]);
        }
        __syncthreads();
    }

#pragma unroll
    for (int mt = 0; mt < 4; mt++) {
        int r = wm * 64 + mt * 16 + g;
#pragma unroll
        for (int nt = 0; nt < 4; nt++) {
            int cc = wn * 32 + nt * 8 + 2 * tg;
            *(float2*)&Cs[r * 132 + cc]       = make_float2(d[mt][nt][0], d[mt][nt][1]);
            *(float2*)&Cs[(r + 8) * 132 + cc] = make_float2(d[mt][nt][2], d[mt][nt][3]);
        }
    }
    __syncthreads();

    {
        const int row = tid >> 1;
        const int half = tid & 1;
        float f[64];
        const float* src = &Cs[row * 132 + half * 64];
#pragma unroll
        for (int j = 0; j < 16; j++) {
            float4 v = *(const float4*)(src + j * 4);
            f[4 * j] = v.x; f[4 * j + 1] = v.y; f[4 * j + 2] = v.z; f[4 * j + 3] = v.w;
        }
        if (mode >= 2) {
            float ssq = 0.f;
#pragma unroll
            for (int j = 0; j < 64; j++) ssq += f[j] * f[j];
            float hs = 1.0f;
            if (mode == 3)   // fold log2e into Q's logit scale (log2-domain softmax)
                hs = expf(fminf(ls[blockIdx.y * 2 + half], 4.6051701859880914f)) * LOG2E;
            float inv = hs / fmaxf(sqrtf(ssq), 1e-12f);
#pragma unroll
            for (int j = 0; j < 64; j++) f[j] *= inv;
        }
        const int m = m0 + row;
        float* dst;
        if (mode == 0) {
            dst = dst_plain + (size_t)m * DM + n0 + half * 64;
        } else {
            int b = m >> 11, t = m & 2047;
            int h = (n0 >> 6) + half;
            float* base = (mode == 1) ? g_vh : (mode == 2) ? g_kn : g_qn;
            dst = base + (((size_t)(b * NH + h)) * TT + t) * DH;
        }
#pragma unroll
        for (int j = 0; j < 16; j++)
            *(float4*)(dst + j * 4) =
                make_float4(f[4 * j], f[4 * j + 1], f[4 * j + 2], f[4 * j + 3]);
    }
}

// ---------------------------------------------------------------------------
// Bias transpose: [T,S,H] -> [H,T,S], scaled by log2e.
// ---------------------------------------------------------------------------
__device__ __forceinline__ void transpose_body(const float* __restrict__ in, float* sm) {
    const int c = blockIdx.y * 32 + blockIdx.x;
    const int tid = threadIdx.x;
    for (int tb = 0; tb < 2; tb++) {
        const int t0 = (c * 2 + tb) * 4;
        for (int s0 = 0; s0 < SS; s0 += 64) {
#pragma unroll
            for (int tt = 0; tt < 4; tt++) {
                const float* src = in + ((size_t)(t0 + tt) * SS + s0) * NH;
#pragma unroll
                for (int p = 0; p < 4; p++) {
                    int idx = p * 256 + tid;
                    int h = idx & 15, ss = idx >> 4;
                    sm[h * 261 + tt * 64 + ss] = src[idx] * LOG2E;
                }
            }
            __syncthreads();
#pragma unroll
            for (int p = 0; p < 16; p++) {
                int idx = p * 256 + tid;
                int ss = idx & 63;
                int combo = idx >> 6;
                int tt = combo & 3, h = combo >> 2;
                g_biasT[(size_t)h * TT * SS + (size_t)(t0 + tt) * SS + s0 + ss] =
                    sm[h * 261 + tt * 64 + ss];
            }
            __syncthreads();
        }
    }
}

__global__ __launch_bounds__(256, 2) void fused_pre_kernel(const float* __restrict__ q,
                                                           const float* __restrict__ k,
                                                           const float* __restrict__ v,
                                                           const float* __restrict__ bias,
                                                           const float* __restrict__ Wqkv,
                                                           const float* __restrict__ ls) {
    extern __shared__ float sm[];
    const int z = blockIdx.z;
    if (z == 0)      gemm_mma_body(q, Wqkv, nullptr, ls, 3, sm);
    else if (z == 1) gemm_mma_body(k, Wqkv, nullptr, nullptr, 2, sm);
    else if (z == 2) gemm_mma_body(v, Wqkv, nullptr, nullptr, 1, sm);
    else             transpose_body(bias, sm);
}

__global__ __launch_bounds__(256, 2) void gemm_out_kernel(const float* __restrict__ Wout,
                                                          float* __restrict__ out) {
    extern __shared__ float sm[];
    gemm_mma_body((const float*)g_vals, Wout, out, nullptr, 0, sm);
}

// ---------------------------------------------------------------------------
// Flash attention v4 (all-tensor): BM=128(t), BN=64(s), 256 thr, 8 warps 4x2.
// QK: mma.sync tf32 (Q,K staged tf32 in NATURAL [m][k]/[n][k] layouts — no
// transpose). S stays in register fragments; exp applied in-register with
// bias read from prefetched Ps in fragment layout; P written to Ps for PV.
// PV: mma.sync tf32 (Vt dh-major). Fixed-offset log2-domain softmax.
// Smem: Qs[128][68] | Ks[64][68] | Vt[64][68] | Ps[128][68] | Ls[2][128].
// ---------------------------------------------------------------------------
#define W68 68
#define ATT_FLOATS (128*W68 + 64*W68 + 64*W68 + 128*W68 + 256)
#define ATT_SMEM (ATT_FLOATS * (int)sizeof(float))

__global__ __launch_bounds__(256, 2) void attention_kernel() {
    extern __shared__ float sm[];
    float* Qs = sm;                         // [128][68] tf32 bits
    float* Ks = sm + 128 * W68;             // [64][68] tf32 bits
    float* Vt = Ks + 64 * W68;              // [64][68] tf32 bits (dh-major)
    float* Ps = Vt + 64 * W68;              // [128][68]  (bias, then P)
    float* Ls = Ps + 128 * W68;             // [2][128]

    const int t0 = blockIdx.x * 128;
    const int h = blockIdx.y;
    const int b = blockIdx.z;
    const int tid = threadIdx.x;
    const int tx = tid & 15, ty = tid >> 4;
    const int wid = tid >> 5, lane = tid & 31;
    const int g = lane >> 2, tg = lane & 3;
    const int wm = wid >> 1, wn = wid & 1;   // 4 x 2 warp grid

    const uint32_t ps_u = s2u(Ps);

    const float* qptr  = g_qn + (((size_t)(b * NH + h)) * TT + t0) * DH;
    const float* kbase = g_kn + ((size_t)(b * NH + h)) * SS * DH;
    const float* vbase = g_vh + ((size_t)(b * NH + h)) * SS * DH;
    const float* bptr  = g_biasT + (size_t)h * TT * SS + (size_t)t0 * SS;

    // Stage Q tile once: natural [m][d] layout, tf32 bits
    {
        int row = tid >> 1;
        int dc0 = (tid & 1) * 32;
        const float* qp = qptr + (size_t)row * DH + dc0;
        uint32_t* Qb = (uint32_t*)Qs;
#pragma unroll
        for (int j = 0; j < 8; j++) {
            float4 v = *(const float4*)(qp + j * 4);
            int c = dc0 + j * 4;
            Qb[row * W68 + c + 0] = f2tf(v.x);
            Qb[row * W68 + c + 1] = f2tf(v.y);
            Qb[row * W68 + c + 2] = f2tf(v.z);
            Qb[row * W68 + c + 3] = f2tf(v.w);
        }
    }

    float lsum[4] = {0.f, 0.f, 0.f, 0.f};
    float o[2][4][4];
#pragma unroll
    for (int mt = 0; mt < 2; mt++)
#pragma unroll
        for (int nt = 0; nt < 4; nt++)
#pragma unroll
            for (int r = 0; r < 4; r++) o[mt][nt][r] = 0.f;

    for (int s0 = 0; s0 < SS; s0 += 64) {
        __syncthreads();   // prev-iter readers of Ks/Vt/Ps done

        // prefetch this tile's bias into Ps via cp.async
#pragma unroll
        for (int i = 0; i < 8; i++) {
            uint32_t dst = ps_u + (uint32_t)(((ty * 8 + i) * W68 + tx * 4) * 4);
            cpa16(dst, bptr + (size_t)(ty * 8 + i) * SS + s0 + tx * 4);
        }
        asm volatile("cp.async.commit_group;" ::: "memory");

        // stage K (natural [s][d]) and V (dh-major [d][s]) as tf32
        {
            int s = tid >> 2;
            int dc = (tid & 3) * 16;
            const float* kp = kbase + (size_t)(s0 + s) * DH + dc;
            const float* vp = vbase + (size_t)(s0 + s) * DH + dc;
            uint32_t* Kb = (uint32_t*)Ks;
            uint32_t* Vb = (uint32_t*)Vt;
#pragma unroll
            for (int q = 0; q < 4; q++) {
                float4 kv = *(const float4*)(kp + q * 4);
                int d = dc + q * 4;
                Kb[s * W68 + d + 0] = f2tf(kv.x);
                Kb[s * W68 + d + 1] = f2tf(kv.y);
                Kb[s * W68 + d + 2] = f2tf(kv.z);
                Kb[s * W68 + d + 3] = f2tf(kv.w);
            }
#pragma unroll
            for (int q = 0; q < 4; q++) {
                float4 vv = *(const float4*)(vp + q * 4);
                int d = dc + q * 4;
                Vb[(d + 0) * W68 + s] = f2tf(vv.x);
                Vb[(d + 1) * W68 + s] = f2tf(vv.y);
                Vb[(d + 2) * W68 + s] = f2tf(vv.z);
                Vb[(d + 3) * W68 + s] = f2tf(vv.w);
            }
        }
        __syncthreads();

        // S = Q K^T via mma.sync tf32 (warp tile 32m x 32n, K-dim 64)
        float sf[2][4][4];
#pragma unroll
        for (int mt = 0; mt < 2; mt++)
#pragma unroll
            for (int nt = 0; nt < 4; nt++)
#pragma unroll
                for (int r = 0; r < 4; r++) sf[mt][nt][r] = 0.f;
        {
            const uint32_t* Qb = (const uint32_t*)Qs;
            const uint32_t* Kb = (const uint32_t*)Ks;
#pragma unroll
            for (int k8 = 0; k8 < 8; k8++) {
                const int k = k8 * 8 + tg;
                uint32_t af[2][4], bf[4][2];
#pragma unroll
                for (int mt = 0; mt < 2; mt++) {
                    int r = wm * 32 + mt * 16 + g;
                    af[mt][0] = Qb[r * W68 + k];
                    af[mt][1] = Qb[(r + 8) * W68 + k];
                    af[mt][2] = Qb[r * W68 + k + 4];
                    af[mt][3] = Qb[(r + 8) * W68 + k + 4];
                }
#pragma unroll
                for (int nt = 0; nt < 4; nt++) {
                    int n = wn * 32 + nt * 8 + g;
                    bf[nt][0] = Kb[n * W68 + k];
                    bf[nt][1] = Kb[n * W68 + k + 4];
                }
#pragma unroll
                for (int mt = 0; mt < 2; mt++)
#pragma unroll
                    for (int nt = 0; nt < 4; nt++)
                        mma8(sf[mt][nt], af[mt], bf[nt]);
            }
        }

        // bias (prefetched) + ex2 in fragment layout; write P into Ps
        asm volatile("cp.async.wait_group 0;" ::: "memory");
        __syncthreads();
#pragma unroll
        for (int mt = 0; mt < 2; mt++) {
            int r0 = wm * 32 + mt * 16 + g;
#pragma unroll
            for (int nt = 0; nt < 4; nt++) {
                int c = wn * 32 + nt * 8 + 2 * tg;
                float2 b0 = *(float2*)&Ps[r0 * W68 + c];
                float2 b1 = *(float2*)&Ps[(r0 + 8) * W68 + c];
                float p00 = ex2(sf[mt][nt][0] + b0.x - FIXC);
                float p01 = ex2(sf[mt][nt][1] + b0.y - FIXC);
                float p10 = ex2(sf[mt][nt][2] + b1.x - FIXC);
                float p11 = ex2(sf[mt][nt][3] + b1.y - FIXC);
                lsum[mt * 2 + 0] += p00 + p01;
                lsum[mt * 2 + 1] += p10 + p11;
                *(float2*)&Ps[r0 * W68 + c]       = make_float2(p00, p01);
                *(float2*)&Ps[(r0 + 8) * W68 + c] = make_float2(p10, p11);
            }
        }
        __syncthreads();

        // O += P V (mma.sync tf32; P raw fp32, HW-truncated)
        {
            const uint32_t* Pr = (const uint32_t*)Ps;
            const uint32_t* Vr = (const uint32_t*)Vt;
#pragma unroll
            for (int kk = 0; kk < 8; kk++) {
                const int k = kk * 8 + tg;
                uint32_t af[2][4];
#pragma unroll
                for (int mt = 0; mt < 2; mt++) {
                    int r = wm * 32 + mt * 16 + g;
                    af[mt][0] = Pr[r * W68 + k];
                    af[mt][1] = Pr[(r + 8) * W68 + k];
                    af[mt][2] = Pr[r * W68 + k + 4];
                    af[mt][3] = Pr[(r + 8) * W68 + k + 4];
                }
#pragma unroll
                for (int nt = 0; nt < 4; nt++) {
                    int n = wn * 32 + nt * 8 + g;
                    uint32_t bf[2];
                    bf[0] = Vr[n * W68 + k];
                    bf[1] = Vr[n * W68 + k + 4];
                    mma8(o[0][nt], af[0], bf);
                    mma8(o[1][nt], af[1], bf);
                }
            }
        }
    }

    // reduce lsum over the 4-lane tg group; publish per-row, per-wn sums
#pragma unroll
    for (int i = 0; i < 4; i++) {
        lsum[i] += __shfl_xor_sync(0xffffffffu, lsum[i], 1);
        lsum[i] += __shfl_xor_sync(0xffffffffu, lsum[i], 2);
    }
    if (tg == 0) {
#pragma unroll
        for (int mt = 0; mt < 2; mt++) {
            int r = wm * 32 + mt * 16 + g;
            Ls[wn * 128 + r]     = lsum[mt * 2 + 0];
            Ls[wn * 128 + r + 8] = lsum[mt * 2 + 1];
        }
    }
    __syncthreads();

    // epilogue: normalize O fragments and write to g_vals [B,T,D]
#pragma unroll
    for (int mt = 0; mt < 2; mt++) {
        int r = wm * 32 + mt * 16 + g;
        float inv0 = 1.0f / (Ls[r] + Ls[128 + r]);
        float inv1 = 1.0f / (Ls[r + 8] + Ls[128 + r + 8]);
        float* d0 = g_vals + ((size_t)(b * TT) + t0 + r) * DM + h * DH;
        float* d1 = g_vals + ((size_t)(b * TT) + t0 + r + 8) * DM + h * DH;
#pragma unroll
        for (int nt = 0; nt < 4; nt++) {
            int c = wn * 32 + nt * 8 + 2 * tg;
            *(float2*)(d0 + c) = make_float2(o[mt][nt][0] * inv0, o[mt][nt][1] * inv0);
            *(float2*)(d1 + c) = make_float2(o[mt][nt][2] * inv1, o[mt][nt][3] * inv1);
        }
    }
}

// ---------------------------------------------------------------------------
extern "C" void kernel_launch(void* const* d_in, const int* in_sizes, int n_in,
                              void* d_out, int out_size) {
    const float* q    = (const float*)d_in[0];
    const float* k    = (const float*)d_in[1];
    const float* v    = (const float*)d_in[2];
    const float* bias = (const float*)d_in[3];
    const float* Wqkv = (const float*)d_in[4];
    const float* Wout = (const float*)d_in[5];
    const float* ls   = (const float*)d_in[6];
    float* out = (float*)d_out;

    cudaFuncSetAttribute(attention_kernel,
                         cudaFuncAttributeMaxDynamicSharedMemorySize, ATT_SMEM);
    cudaFuncSetAttribute(fused_pre_kernel,
                         cudaFuncAttributeMaxDynamicSharedMemorySize, PRE_SMEM);
    cudaFuncSetAttribute(gemm_out_kernel,
                         cudaFuncAttributeMaxDynamicSharedMemorySize, PRE_SMEM);

    fused_pre_kernel<<<dim3(32, 8, 4), 256, PRE_SMEM>>>(q, k, v, bias, Wqkv, ls);

    attention_kernel<<<dim3(TT / 128, NH, BB), 256, ATT_SMEM>>>();

    gemm_out_kernel<<<dim3(32, 8), 256, PRE_SMEM>>>(Wout, out);
}